// round 7
// baseline (speedup 1.0000x reference)
#include <cuda_runtime.h>

// MPM p2g scatter: 1M particles -> 128^3 grid of (mass, mom.x, mom.y, mom.z)
// R6: split each warp-wide scattered REDG (18 distinct lines -> 17 replays
// at ~2.07 cyc each, the measured binder) into 16 predicated REDGs, each
// activating one z-pair (2 lanes -> ~1 line -> ~no replays). Total wavefronts
// unchanged (4.5/particle, the coalescing floor) but they drain at the
// ~1.0 cyc/wf cross-instruction rate instead of the replay rate.

static constexpr float INV_CELL = 64.0f;

// Predicated vector reduction: only lanes whose pair-id == g execute.
__device__ __forceinline__ void red_add_v4_pair(
    float* p, float a, float b, float c, float d, int pid, int g)
{
    asm volatile("{\n\t"
                 ".reg .pred q;\n\t"
                 "setp.eq.s32 q, %5, %6;\n\t"
                 "@q red.global.add.v4.f32 [%0], {%1, %2, %3, %4};\n\t"
                 "}"
                 :: "l"(p), "f"(a), "f"(b), "f"(c), "f"(d), "r"(pid), "r"(g)
                 : "memory");
}

// Per-warp staging: pos[96] | vel[96] | mass[32] floats = 224 floats (896B).
static constexpr int WARP_STAGE = 224;

__global__ __launch_bounds__(256) void p2g_corner_kernel(
    const float* __restrict__ pos,
    const float* __restrict__ vel,
    const float* __restrict__ mass,
    float* __restrict__ out,
    int n)
{
    __shared__ float stage[8 * WARP_STAGE];   // 8 warps/block

    int warp_id = (blockIdx.x * blockDim.x + threadIdx.x) >> 5;  // global warp
    int lane = threadIdx.x & 31;
    int wib = threadIdx.x >> 5;               // warp in block
    float* sp = stage + wib * WARP_STAGE;     // [0,96) pos, [96,192) vel, [192,224) mass

    int base = warp_id * 32;                  // 32 particles per warp
    if (base >= n) return;

    // ---- cooperative load: 3 coalesced LDG.128 instructions per warp ----
    if (base + 32 <= n) {
        const float4* pos4 = (const float4*)pos;
        const float4* vel4 = (const float4*)vel;
        const float4* mass4 = (const float4*)mass;
        if (lane < 24) {
            ((float4*)sp)[lane]        = pos4[warp_id * 24 + lane];   // 96 floats
            ((float4*)(sp + 96))[lane] = vel4[warp_id * 24 + lane];   // 96 floats
        } else {
            ((float4*)(sp + 192))[lane - 24] = mass4[warp_id * 8 + (lane - 24)]; // 32 floats
        }
    } else {
        // tail warp: scalar guarded loads (rare path)
        int nv = n - base;                    // 1..31 valid particles
        for (int e = lane; e < nv * 3; e += 32) {
            sp[e]      = pos[base * 3 + e];
            sp[96 + e] = vel[base * 3 + e];
        }
        if (lane < nv) sp[192 + lane] = mass[base + lane];
    }
    __syncwarp();

    // ---- corner-parallel scatter: 8 lanes/particle, 4 particles/round ----
    // lane = pid*2 + z: bit0=z, bits1-2=xy-combo, bits3-4=particle-in-round.
    int p_local = lane >> 3;                  // particle within round
    int c = lane & 7;                         // corner: bit0=z, bit1=x, bit2=y
    int cz = c & 1;
    int cx = (c >> 1) & 1;
    int cy = (c >> 2) & 1;
    int pid = lane >> 1;                      // z-pair id, 0..15

#pragma unroll
    for (int s = 0; s < 8; s++) {
        int idx = s * 4 + p_local;            // particle index within warp
        if (base + idx < n) {
            // broadcast LDS (conflict-free: 4 distinct banks, 8-way bcast)
            float px = sp[3 * idx + 0];
            float py = sp[3 * idx + 1];
            float pz = sp[3 * idx + 2];
            float vx = sp[96 + 3 * idx + 0];
            float vy = sp[96 + 3 * idx + 1];
            float vz = sp[96 + 3 * idx + 2];
            float m  = sp[192 + idx];

            float rx = px * INV_CELL;
            float ry = py * INV_CELL;
            float rz = pz * INV_CELL;
            float bx = floorf(rx), by = floorf(ry), bz = floorf(rz);
            float fx = rx - bx, fy = ry - by, fz = rz - bz;

            float wxv = cx ? fx : 1.f - fx;
            float wyv = cy ? fy : 1.f - fy;
            float wzv = cz ? fz : 1.f - fz;

            // hash = z + x*128 + y*128*128 (all corners guaranteed in range)
            int hash = ((int)bz + cz) + (((int)bx + cx) << 7) + (((int)by + cy) << 14);

            float sm = wxv * wyv * wzv * m;
            float* addr = out + 4 * hash;
            float m0 = sm, m1 = sm * vx, m2 = sm * vy, m3 = sm * vz;

            // 16 predicated single-line REDGs instead of one 18-line REDG:
            // converts replay-priced wavefronts into pipeline-priced ones.
#pragma unroll
            for (int g = 0; g < 16; g++)
                red_add_v4_pair(addr, m0, m1, m2, m3, pid, g);
        }
    }
}

extern "C" void kernel_launch(void* const* d_in, const int* in_sizes, int n_in,
                              void* d_out, int out_size) {
    const float* pos  = (const float*)d_in[0];
    const float* vel  = (const float*)d_in[1];
    const float* mass = (const float*)d_in[2];
    float* out = (float*)d_out;

    // Zero the accumulation grid (memset node in the graph; no alloc).
    cudaMemsetAsync(d_out, 0, (size_t)out_size * sizeof(float));

    int n = in_sizes[2];                     // mass count = NUM_POINTS
    int warps = (n + 31) / 32;               // 32 particles per warp
    int blocks = (warps + 7) / 8;            // 8 warps (256 threads) per block
    p2g_corner_kernel<<<blocks, 256>>>(pos, vel, mass, out, n);
}

// round 8
// speedup vs baseline: 2.0123x; 2.0123x over previous
#include <cuda_runtime.h>

// MPM p2g scatter: 1M particles -> 128^3 grid of (mass, mom.x, mom.y, mom.z)
// R7: R5 structure (corner-parallel v4 REDG — at the REDG wavefront floor of
// 4.5 lines/particle x 2.07 cyc), minus everything else:
//  - particle data staged as two float4s: (fx,fy,fz,m), (vx,vy,vz,base-hash)
//    -> 2 conflict-free broadcast LDS.128 per round instead of 7 LDS.32
//  - floor/frac/base-hash computed ONCE per particle in a staging pass,
//    not redundantly in 8 lanes x 8 rounds
//  - branch-free corner weights via fma(+-1, f, c); corner hash = base + const
// R6 lesson (reverted): splitting REDGs costs ~5 cyc/instr dispatch; total
// line-touches are fixed, so fewer, wider REDG instructions are optimal.

static constexpr float INV_CELL = 64.0f;

__device__ __forceinline__ void red_add_v4(float* p, float a, float b, float c, float d) {
    asm volatile("red.global.add.v4.f32 [%0], {%1, %2, %3, %4};"
                 :: "l"(p), "f"(a), "f"(b), "f"(c), "f"(d)
                 : "memory");
}

// Per-warp staging: pm[32] float4 + vl[32] float4 = 1KB/warp.
static constexpr int WARP_F4 = 64;  // 64 float4 per warp

__global__ __launch_bounds__(256) void p2g_corner_kernel(
    const float* __restrict__ pos,
    const float* __restrict__ vel,
    const float* __restrict__ mass,
    float* __restrict__ out,
    int n)
{
    __shared__ float4 stage[8 * WARP_F4];     // 8 warps/block

    int warp_id = (blockIdx.x * blockDim.x + threadIdx.x) >> 5;
    int lane = threadIdx.x & 31;
    int wib = threadIdx.x >> 5;
    float4* pm = stage + wib * WARP_F4;       // (fx,fy,fz,m) per particle
    float4* vl = pm + 32;                     // (vx,vy,vz,bitcast(base)) per particle
    float* pmf = (float*)pm;
    float* vlf = (float*)vl;

    int base = warp_id * 32;                  // 32 particles per warp
    if (base >= n) return;

    if (base + 32 <= n) {
        // ---- Stage A: cooperative coalesced load + AoS->padded repack ----
        const float4* pos4 = (const float4*)pos;
        const float4* vel4 = (const float4*)vel;
        const float4* mass4 = (const float4*)mass;
        if (lane < 24) {
            float4 p4 = pos4[warp_id * 24 + lane];   // floats j=4*lane..+3
            float4 v4 = vel4[warp_id * 24 + lane];
            int j = 4 * lane;
#pragma unroll
            for (int t = 0; t < 4; t++) {
                int q = (j + t) / 3, r = (j + t) % 3;
                pmf[q * 4 + r] = (&p4.x)[t] * INV_CELL;   // rel coords
                vlf[q * 4 + r] = (&v4.x)[t];
            }
        } else {
            float4 m4 = mass4[warp_id * 8 + (lane - 24)];
            int q0 = 4 * (lane - 24);
#pragma unroll
            for (int t = 0; t < 4; t++)
                pmf[(q0 + t) * 4 + 3] = (&m4.x)[t];
        }
        __syncwarp();

        // ---- Stage B: per-particle floor/frac/base-hash, once ----
        {
            float4 r4 = pm[lane];
            float bx = floorf(r4.x), by = floorf(r4.y), bz = floorf(r4.z);
            int bh = (int)bz + ((int)bx << 7) + ((int)by << 14);
            pm[lane] = make_float4(r4.x - bx, r4.y - by, r4.z - bz, r4.w);
            vlf[lane * 4 + 3] = __int_as_float(bh);
        }
        __syncwarp();

        // ---- corner-parallel scatter: 8 lanes/particle, 4 particles/instr ----
        int p_local = lane >> 3;
        int c = lane & 7;                     // bit0=z, bit1=x, bit2=y
        int cz = c & 1, cx = (c >> 1) & 1, cy = (c >> 2) & 1;
        // weight = cx ? f : 1-f  ==  fma(ax, f, bx)
        float axw = cx ? 1.f : -1.f, bxw = cx ? 0.f : 1.f;
        float ayw = cy ? 1.f : -1.f, byw = cy ? 0.f : 1.f;
        float azw = cz ? 1.f : -1.f, bzw = cz ? 0.f : 1.f;
        int coff = cz + (cx << 7) + (cy << 14);

#pragma unroll
        for (int s = 0; s < 8; s++) {
            int idx = s * 4 + p_local;
            float4 f4 = pm[idx];              // LDS.128, conflict-free, bcast
            float4 v4 = vl[idx];
            float wx = fmaf(axw, f4.x, bxw);
            float wy = fmaf(ayw, f4.y, byw);
            float wz = fmaf(azw, f4.z, bzw);
            float sm = wx * wy * wz * f4.w;
            int hash = __float_as_int(v4.w) + coff;
            red_add_v4(out + 4 * hash, sm, sm * v4.x, sm * v4.y, sm * v4.z);
        }
    } else {
        // ---- tail warp (not hit for n % 32 == 0): per-lane scalar path ----
        int pidx = base + lane;
        if (pidx < n) {
            float rx = pos[3 * pidx + 0] * INV_CELL;
            float ry = pos[3 * pidx + 1] * INV_CELL;
            float rz = pos[3 * pidx + 2] * INV_CELL;
            float vx = vel[3 * pidx + 0];
            float vy = vel[3 * pidx + 1];
            float vz = vel[3 * pidx + 2];
            float m  = mass[pidx];
            float bx = floorf(rx), by = floorf(ry), bz = floorf(rz);
            float fx = rx - bx, fy = ry - by, fz = rz - bz;
            int bh = (int)bz + ((int)bx << 7) + ((int)by << 14);
#pragma unroll
            for (int cc = 0; cc < 8; cc++) {
                int z = cc & 1, x = (cc >> 1) & 1, y = (cc >> 2) & 1;
                float w = (x ? fx : 1.f - fx) * (y ? fy : 1.f - fy) * (z ? fz : 1.f - fz);
                float sm = w * m;
                int hash = bh + z + (x << 7) + (y << 14);
                red_add_v4(out + 4 * hash, sm, sm * vx, sm * vy, sm * vz);
            }
        }
    }
}

extern "C" void kernel_launch(void* const* d_in, const int* in_sizes, int n_in,
                              void* d_out, int out_size) {
    const float* pos  = (const float*)d_in[0];
    const float* vel  = (const float*)d_in[1];
    const float* mass = (const float*)d_in[2];
    float* out = (float*)d_out;

    // Zero the accumulation grid (memset node in the graph; no alloc).
    cudaMemsetAsync(d_out, 0, (size_t)out_size * sizeof(float));

    int n = in_sizes[2];                      // mass count = NUM_POINTS
    int warps = (n + 31) / 32;
    int blocks = (warps + 7) / 8;             // 8 warps (256 threads) per block
    p2g_corner_kernel<<<blocks, 256>>>(pos, vel, mass, out, n);
}